// round 10
// baseline (speedup 1.0000x reference)
#include <cuda_runtime.h>
#include <cstdint>

// ============ NuggetScorer — R10: TF32 approx rank + exact fp32 rescore ======
#define BB 8
#define SS 4096
#define DD 2048
#define HH 128
#define MN 410
#define MM (BB*SS)

#define ENC_SZ ((size_t)BB*MN*DD)
#define BMN (BB*MN)

#define NCAND 512
#define CPB 16                 // candidates per rescore block

// GEMM config (2-level TF32 split, 3 terms)
#define KC 16
#define NCH (DD/KC)            // 128
#define LVLF 2048
#define AFRAG (2*LVLF)         // 4096
#define BFRAG (2*LVLF)         // 4096
#define STAGEF (AFRAG+BFRAG)   // 8192
#define REDF (128*17)
#define SMEM_FLOATS (2*STAGEF + REDF + 256)
#define SMEM_BYTES (SMEM_FLOATS*4)

__device__ float r10_bfrag[NCH*BFRAG];
__device__ float r10_w1t[HH*DD];      // W1 transposed [n][k] fp32 exact
__device__ float r10_scores[MM];      // approx scores
__device__ int   r10_cand[BB*NCAND];
__device__ float r10_cscore[BB*NCAND];
__device__ int   r10_nn[BB];
__device__ int   r10_idx[BB*MN];

typedef unsigned long long ull;

__device__ __forceinline__ float r10_tf32(float x) {
    uint32_t r; asm("cvt.rna.tf32.f32 %0,%1;" : "=r"(r) : "f"(x));
    return __uint_as_float(r);
}
__device__ __forceinline__ void r10_mma(float* d, const uint32_t* a, const uint32_t* b) {
    asm volatile("mma.sync.aligned.m16n8k8.row.col.f32.tf32.tf32.f32 "
        "{%0,%1,%2,%3},{%4,%5,%6,%7},{%8,%9},{%0,%1,%2,%3};"
        : "+f"(d[0]), "+f"(d[1]), "+f"(d[2]), "+f"(d[3])
        : "r"(a[0]), "r"(a[1]), "r"(a[2]), "r"(a[3]), "r"(b[0]), "r"(b[1]));
}

// ---------------------------------------------------------------------------
// Kernel 0: W1 prep — 2-level tf32 fragments + exact fp32 transpose
// ---------------------------------------------------------------------------
__global__ __launch_bounds__(256) void r10_bprep(const float* __restrict__ w1)
{
    int idx = blockIdx.x * 256 + threadIdx.x;    // 0 .. 262143
    int k = idx >> 7, n = idx & 127;
    float x = w1[idx];                            // w1[k][n]
    r10_w1t[(size_t)n * DD + k] = x;
    float h0 = r10_tf32(x);
    float h1 = r10_tf32(x - h0);
    int ch = k >> 4, kk = k & 15;
    int ks = kk >> 3, c2 = kk & 7;
    int nb = n >> 3;
    int lane = ((n & 7) << 2) | (c2 & 3);
    int slot = c2 >> 2;
    int base = ch * BFRAG + ((nb * 2 + ks) << 6) + (lane << 1) + slot;
    r10_bfrag[base]        = h0;
    r10_bfrag[base + LVLF] = h1;
}

// ---------------------------------------------------------------------------
// Kernel 1: approx score GEMM, 3-term 2-level TF32 (mma.sync).
// ---------------------------------------------------------------------------
extern __shared__ float r10_dsm[];

__global__ __launch_bounds__(256) void r10_score(
    const float* __restrict__ A, const float* __restrict__ bias1,
    const float* __restrict__ w2v, const float* __restrict__ bias2,
    float* __restrict__ scores_out)
{
    const int tid  = threadIdx.x;
    const int lane = tid & 31;
    const int wid  = tid >> 5;
    const int wy   = wid >> 2;
    const int wx   = wid & 3;
    const int row0 = blockIdx.x * 128;

    float* red = r10_dsm + 2 * STAGEF;
    float* b1s = red + REDF;
    float* w2s = b1s + HH;
    if (tid < HH) { b1s[tid] = bias1[tid]; w2s[tid] = w2v[tid]; }

    const int rr0 = tid >> 2;
    const int q   = tid & 3;
    int aoff[8];
#pragma unroll
    for (int e = 0; e < 8; e++) {
        int rr = (e < 4) ? rr0 : rr0 + 64;
        int col = q * 4 + (e & 3);
        int ks = col >> 3, cc = col & 7;
        int mt = rr >> 4, r = rr & 15;
        int lw = ((r & 7) << 2) | (cc & 3);
        int slot = ((cc >> 2) << 1) | (r >> 3);
        aoff[e] = ((mt * 2 + ks) << 7) + (lw << 2) + slot;
    }

    float acc[4][4][4];
#pragma unroll
    for (int i = 0; i < 4; i++)
#pragma unroll
        for (int j = 0; j < 4; j++)
#pragma unroll
            for (int v = 0; v < 4; v++) acc[i][j][v] = 0.f;

    float4 sa0, sa1, sb[4];

    sa0 = *(const float4*)(A + (size_t)(row0 + rr0) * DD + q * 4);
    sa1 = *(const float4*)(A + (size_t)(row0 + rr0 + 64) * DD + q * 4);
#pragma unroll
    for (int i = 0; i < 4; i++)
        sb[i] = __ldg((const float4*)(r10_bfrag + (size_t)(tid + i * 256) * 4));

    {
        float* st = r10_dsm;
        float av[8] = {sa0.x, sa0.y, sa0.z, sa0.w, sa1.x, sa1.y, sa1.z, sa1.w};
#pragma unroll
        for (int e = 0; e < 8; e++) {
            float x = av[e];
            float h0 = r10_tf32(x);
            float h1 = r10_tf32(x - h0);
            st[aoff[e]]        = h0;
            st[aoff[e] + LVLF] = h1;
        }
#pragma unroll
        for (int i = 0; i < 4; i++)
            *(float4*)(st + AFRAG + (tid + i * 256) * 4) = sb[i];
    }
    __syncthreads();

    for (int c = 0; c < NCH; ++c) {
        const int cur = c & 1;
        const float* st = r10_dsm + cur * STAGEF;

        if (c + 1 < NCH) {
            int k0 = (c + 1) * KC;
            sa0 = *(const float4*)(A + (size_t)(row0 + rr0) * DD + k0 + q * 4);
            sa1 = *(const float4*)(A + (size_t)(row0 + rr0 + 64) * DD + k0 + q * 4);
#pragma unroll
            for (int i = 0; i < 4; i++)
                sb[i] = __ldg((const float4*)(r10_bfrag + (size_t)(c + 1) * BFRAG + (size_t)(tid + i * 256) * 4));
        }

#pragma unroll
        for (int ks = 0; ks < 2; ks++) {
            const float* Ab = st;
            const float* Bb = st + AFRAG;
            uint32_t a0[4][4], a1[4][4], b0[4][2], b1r[4][2];
#pragma unroll
            for (int mt = 0; mt < 4; mt++) {
                float4 v = *(const float4*)(Ab + (((wy * 4 + mt) * 2 + ks) << 7) + (lane << 2));
                a0[mt][0] = __float_as_uint(v.x); a0[mt][1] = __float_as_uint(v.y);
                a0[mt][2] = __float_as_uint(v.z); a0[mt][3] = __float_as_uint(v.w);
                float4 w = *(const float4*)(Ab + LVLF + (((wy * 4 + mt) * 2 + ks) << 7) + (lane << 2));
                a1[mt][0] = __float_as_uint(w.x); a1[mt][1] = __float_as_uint(w.y);
                a1[mt][2] = __float_as_uint(w.z); a1[mt][3] = __float_as_uint(w.w);
            }
#pragma unroll
            for (int nt = 0; nt < 4; nt++) {
                float2 v = *(const float2*)(Bb + (((wx * 4 + nt) * 2 + ks) << 6) + (lane << 1));
                b0[nt][0] = __float_as_uint(v.x); b0[nt][1] = __float_as_uint(v.y);
                float2 w = *(const float2*)(Bb + LVLF + (((wx * 4 + nt) * 2 + ks) << 6) + (lane << 1));
                b1r[nt][0] = __float_as_uint(w.x); b1r[nt][1] = __float_as_uint(w.y);
            }
#pragma unroll
            for (int mt = 0; mt < 4; mt++)
#pragma unroll
                for (int nt = 0; nt < 4; nt++) {
                    r10_mma(acc[mt][nt], a0[mt], b0[nt]);
                    r10_mma(acc[mt][nt], a0[mt], b1r[nt]);
                    r10_mma(acc[mt][nt], a1[mt], b0[nt]);
                }
        }

        if (c + 1 < NCH) {
            float* st2 = r10_dsm + (cur ^ 1) * STAGEF;
            float av[8] = {sa0.x, sa0.y, sa0.z, sa0.w, sa1.x, sa1.y, sa1.z, sa1.w};
#pragma unroll
            for (int e = 0; e < 8; e++) {
                float x = av[e];
                float h0 = r10_tf32(x);
                float h1 = r10_tf32(x - h0);
                st2[aoff[e]]        = h0;
                st2[aoff[e] + LVLF] = h1;
            }
#pragma unroll
            for (int i = 0; i < 4; i++)
                *(float4*)(st2 + AFRAG + (tid + i * 256) * 4) = sb[i];
        }
        __syncthreads();
    }

    const int mrow = lane >> 2;
    const int kcol = lane & 3;
#pragma unroll
    for (int mt = 0; mt < 4; mt++)
#pragma unroll
        for (int h = 0; h < 2; h++) {
            int row = (wy * 4 + mt) * 16 + mrow + 8 * h;
            float part = 0.f;
#pragma unroll
            for (int nt = 0; nt < 4; nt++) {
                int col = (wx * 4 + nt) * 8 + 2 * kcol;
                float x0 = acc[mt][nt][2 * h]     + b1s[col];
                float x1 = acc[mt][nt][2 * h + 1] + b1s[col + 1];
                float g0 = 0.5f * x0 * (1.0f + erff(x0 * 0.7071067811865476f));
                float g1 = 0.5f * x1 * (1.0f + erff(x1 * 0.7071067811865476f));
                part = fmaf(g0, w2s[col], part);
                part = fmaf(g1, w2s[col + 1], part);
            }
            red[row * 17 + wx * 4 + kcol] = part;
        }
    __syncthreads();

    if (tid < 128) {
        float s = bias2[0];
#pragma unroll
        for (int j = 0; j < 16; j++) s += red[tid * 17 + j];
        scores_out[row0 + tid] = s;
        r10_scores[row0 + tid] = s;
    }
}

// ---------------------------------------------------------------------------
// Kernel 2: per-batch bitonic sort of approx scores -> top-NCAND candidates.
// ---------------------------------------------------------------------------
__global__ __launch_bounds__(1024) void r10_cand_topk(const int* __restrict__ mask)
{
    __shared__ ull key[SS];
    __shared__ int sh_cnt;
    const int b = blockIdx.x;
    const int tid = threadIdx.x;
    if (tid == 0) sh_cnt = 0;
    __syncthreads();

    const float* srow = r10_scores + (size_t)b * SS;
    const int*   mrow = mask + (size_t)b * SS;

    int cnt = 0;
    for (int i = tid; i < SS; i += 1024) {
        float f = srow[i];
        unsigned u = __float_as_uint(f);
        u = (u & 0x80000000u) ? ~u : (u | 0x80000000u);
        key[i] = ((ull)u << 12) | (ull)(SS - 1 - i);
        cnt += mrow[i];
    }
#pragma unroll
    for (int o = 16; o > 0; o >>= 1) cnt += __shfl_down_sync(0xffffffffu, cnt, o);
    if ((tid & 31) == 0) atomicAdd(&sh_cnt, cnt);
    __syncthreads();

    for (int k = 2; k <= SS; k <<= 1) {
        for (int j = k >> 1; j > 0; j >>= 1) {
            for (int i = tid; i < SS; i += 1024) {
                int l = i ^ j;
                if (l > i) {
                    ull a = key[i], cc = key[l];
                    bool desc = ((i & k) == 0);
                    if (desc ? (a < cc) : (a > cc)) { key[i] = cc; key[l] = a; }
                }
            }
            __syncthreads();
        }
    }

    if (tid == 0) {
        int ntok = sh_cnt;
        int nn = (int)ceilf((float)ntok * 0.1f);
        nn = max(nn, 1);
        nn = min(nn, ntok);
        r10_nn[b] = nn;
    }
    if (tid < NCAND)
        r10_cand[b * NCAND + tid] = (SS - 1) - (int)(key[tid] & 0xFFFull);
}

// ---------------------------------------------------------------------------
// Kernel 3: exact fp32 rescore of candidates (serial-k FFMA, matches ref class)
// block = 128 threads (one per hidden col), CPB candidates per block.
// ---------------------------------------------------------------------------
__global__ __launch_bounds__(128) void r10_rescore(
    const float* __restrict__ lhs, const float* __restrict__ bias1,
    const float* __restrict__ w2v, const float* __restrict__ bias2)
{
    __shared__ float sA[CPB][128];
    __shared__ float sp[128][CPB];

    const int blk = blockIdx.x;                 // 0 .. BB*NCAND/CPB-1
    const int tid = threadIdx.x;                // hidden column j
    const int cand0 = blk * CPB;
    const int b = cand0 / NCAND;

    float h[CPB];
#pragma unroll
    for (int r = 0; r < CPB; r++) h[r] = 0.f;

    const float* wrow = r10_w1t + (size_t)tid * DD;

    for (int ch = 0; ch < DD / 128; ch++) {
        __syncthreads();
        // load CPB x 128 A chunk (512 float4, 4 per thread)
#pragma unroll
        for (int p = 0; p < 4; p++) {
            int lin = tid + p * 128;            // 0..511
            int r = lin >> 5, qq = lin & 31;
            int rowidx = r10_cand[cand0 + r];
            *(float4*)(&sA[r][qq * 4]) =
                *(const float4*)(lhs + ((size_t)b * SS + rowidx) * DD + ch * 128 + qq * 4);
        }
        __syncthreads();

#pragma unroll 8
        for (int q4 = 0; q4 < 32; q4++) {
            float4 w = __ldg((const float4*)(wrow + ch * 128 + q4 * 4));
#pragma unroll
            for (int r = 0; r < CPB; r++) {
                float4 a = *(const float4*)(&sA[r][q4 * 4]);
                h[r] = fmaf(a.x, w.x, h[r]);
                h[r] = fmaf(a.y, w.y, h[r]);
                h[r] = fmaf(a.z, w.z, h[r]);
                h[r] = fmaf(a.w, w.w, h[r]);
            }
        }
    }

    float b1v = bias1[tid], w2vv = w2v[tid];
#pragma unroll
    for (int r = 0; r < CPB; r++) {
        float x = h[r] + b1v;
        float g = 0.5f * x * (1.0f + erff(x * 0.7071067811865476f));
        sp[tid][r] = g * w2vv;
    }
    __syncthreads();

    if (tid < CPB) {
        float s = bias2[0];
        for (int j = 0; j < 128; j++) s += sp[j][tid];
        r10_cscore[cand0 + tid] = s;
    }
}

// ---------------------------------------------------------------------------
// Kernel 4: final per-batch sort of NCAND rescored candidates -> outputs.
// ---------------------------------------------------------------------------
__global__ __launch_bounds__(NCAND) void r10_final(
    float* __restrict__ o_mask, float* __restrict__ o_ns, float* __restrict__ o_idx)
{
    __shared__ ull key[NCAND];
    const int b = blockIdx.x;
    const int tid = threadIdx.x;

    {
        float f = r10_cscore[b * NCAND + tid];
        int idx = r10_cand[b * NCAND + tid];
        unsigned u = __float_as_uint(f);
        u = (u & 0x80000000u) ? ~u : (u | 0x80000000u);
        key[tid] = ((ull)u << 12) | (ull)(SS - 1 - idx);
    }
    __syncthreads();

    for (int k = 2; k <= NCAND; k <<= 1) {
        for (int j = k >> 1; j > 0; j >>= 1) {
            int l = tid ^ j;
            if (l > tid) {
                ull a = key[tid], cc = key[l];
                bool desc = ((tid & k) == 0);
                if (desc ? (a < cc) : (a > cc)) { key[tid] = cc; key[l] = a; }
            }
            __syncthreads();
        }
    }

    if (tid < MN) {
        ull kk = key[tid];
        int idx = (SS - 1) - (int)(kk & 0xFFFull);
        unsigned u = (unsigned)(kk >> 12);
        u = (u & 0x80000000u) ? (u & 0x7FFFFFFFu) : ~u;
        int nn = r10_nn[b];
        o_idx[b * MN + tid]  = (float)idx;
        o_ns[b * MN + tid]   = __uint_as_float(u);
        o_mask[b * MN + tid] = (tid < nn) ? 1.0f : 0.0f;
        r10_idx[b * MN + tid] = idx;
    }
}

// ---------------------------------------------------------------------------
// Kernel 5: gather enc rows.
// ---------------------------------------------------------------------------
__global__ __launch_bounds__(512) void r10_gather(
    const float* __restrict__ hidden, float* __restrict__ enc)
{
    int t = blockIdx.x;
    int b = t / MN;
    int s = r10_idx[t];
    const float4* src = (const float4*)(hidden + ((size_t)b * SS + s) * DD);
    float4* dst = (float4*)(enc + (size_t)t * DD);
    dst[threadIdx.x] = src[threadIdx.x];
}

// ---------------------------------------------------------------------------
extern "C" void kernel_launch(void* const* d_in, const int* in_sizes, int n_in,
                              void* d_out, int out_size)
{
    const float* lhs  = (const float*)d_in[0];
    const float* hid  = (const float*)d_in[1];
    const int*   mask = (const int*)  d_in[2];
    const float* w1   = (const float*)d_in[3];
    const float* b1   = (const float*)d_in[4];
    const float* w2   = (const float*)d_in[5];
    const float* b2   = (const float*)d_in[6];

    float* out = (float*)d_out;
    float* o_enc    = out;
    float* o_mask   = out + ENC_SZ;
    float* o_ns     = o_mask + BMN;
    float* o_idx    = o_ns + BMN;
    float* o_scores = o_idx + BMN;

    cudaFuncSetAttribute(r10_score,
                         cudaFuncAttributeMaxDynamicSharedMemorySize, SMEM_BYTES);

    r10_bprep<<<(HH * DD) / 256, 256>>>(w1);
    r10_score<<<MM / 128, 256, SMEM_BYTES>>>(lhs, b1, w2, b2, o_scores);
    r10_cand_topk<<<BB, 1024>>>(mask);
    r10_rescore<<<BB * NCAND / CPB, 128>>>(lhs, b1, w2, b2);
    r10_final<<<BB, NCAND>>>(o_mask, o_ns, o_idx);
    r10_gather<<<BB * MN, 512>>>(hid, o_enc);
}

// round 12
// speedup vs baseline: 1.2675x; 1.2675x over previous
#include <cuda_runtime.h>
#include <cstdint>

// ====== NuggetScorer — R12: 1-term TF32 rank + exact fp32 rescore ===========
#define BB 8
#define SS 4096
#define DD 2048
#define HH 128
#define MN 410
#define MM (BB*SS)

#define ENC_SZ ((size_t)BB*MN*DD)
#define BMN (BB*MN)

#define NCAND 512
#define CPB 16                 // candidates per rescore block
#define ASTRIDE 18             // smem row stride (floats): even -> 8B-aligned pairs

// GEMM config (single-level TF32)
#define KC 16
#define NCH (DD/KC)            // 128
#define LVLF 2048
#define AFRAG LVLF             // 2048
#define BFRAG LVLF             // 2048
#define STAGEF (AFRAG+BFRAG)   // 4096
#define REDF (128*17)
#define SMEM_FLOATS (2*STAGEF + REDF + 256)
#define SMEM_BYTES (SMEM_FLOATS*4)

__device__ float r12_bfrag[NCH*BFRAG];
__device__ float r12_scores[MM];
__device__ int   r12_cand[BB*NCAND];
__device__ float r12_cscore[BB*NCAND];
__device__ int   r12_nn[BB];
__device__ int   r12_idx[BB*MN];

typedef unsigned long long ull;

__device__ __forceinline__ float r12_tf32(float x) {
    uint32_t r; asm("cvt.rna.tf32.f32 %0,%1;" : "=r"(r) : "f"(x));
    return __uint_as_float(r);
}
__device__ __forceinline__ void r12_mma(float* d, const uint32_t* a, const uint32_t* b) {
    asm volatile("mma.sync.aligned.m16n8k8.row.col.f32.tf32.tf32.f32 "
        "{%0,%1,%2,%3},{%4,%5,%6,%7},{%8,%9},{%0,%1,%2,%3};"
        : "+f"(d[0]), "+f"(d[1]), "+f"(d[2]), "+f"(d[3])
        : "r"(a[0]), "r"(a[1]), "r"(a[2]), "r"(a[3]), "r"(b[0]), "r"(b[1]));
}
__device__ __forceinline__ ull r12_pack2(float x, float y) {
    ull r; asm("mov.b64 %0,{%1,%2};" : "=l"(r) : "f"(x), "f"(y)); return r;
}
__device__ __forceinline__ void r12_unpack2(ull v, float& x, float& y) {
    asm("mov.b64 {%0,%1},%2;" : "=f"(x), "=f"(y) : "l"(v));
}
__device__ __forceinline__ void r12_ffma2(ull& d, ull a, ull b) {
    asm("fma.rn.f32x2 %0,%1,%2,%0;" : "+l"(d) : "l"(a), "l"(b));
}

// ---------------------------------------------------------------------------
// Kernel 0: W1 -> single-level tf32 fragments (fragment-major per chunk)
// ---------------------------------------------------------------------------
__global__ __launch_bounds__(256) void r12_bprep(const float* __restrict__ w1)
{
    int idx = blockIdx.x * 256 + threadIdx.x;    // 0 .. 262143
    int k = idx >> 7, n = idx & 127;
    float h0 = r12_tf32(w1[idx]);                 // w1[k][n]
    int ch = k >> 4, kk = k & 15;
    int ks = kk >> 3, c2 = kk & 7;
    int nb = n >> 3;
    int lane = ((n & 7) << 2) | (c2 & 3);
    int slot = c2 >> 2;
    r12_bfrag[ch * BFRAG + ((nb * 2 + ks) << 6) + (lane << 1) + slot] = h0;
}

// ---------------------------------------------------------------------------
// Kernel 1: approx score GEMM, single-term TF32 (mma.sync).
// BM=128, BN=128, KC=16. 256 threads, 8 warps (2m x 4n), warp tile 64x32.
// ---------------------------------------------------------------------------
extern __shared__ float r12_dsm[];

__global__ __launch_bounds__(256) void r12_score(
    const float* __restrict__ A, const float* __restrict__ bias1,
    const float* __restrict__ w2v, const float* __restrict__ bias2,
    float* __restrict__ scores_out)
{
    const int tid  = threadIdx.x;
    const int lane = tid & 31;
    const int wid  = tid >> 5;
    const int wy   = wid >> 2;
    const int wx   = wid & 3;
    const int row0 = blockIdx.x * 128;

    float* red = r12_dsm + 2 * STAGEF;
    float* b1s = red + REDF;
    float* w2s = b1s + HH;
    if (tid < HH) { b1s[tid] = bias1[tid]; w2s[tid] = w2v[tid]; }

    const int rr0 = tid >> 2;
    const int q   = tid & 3;
    int aoff[8];
#pragma unroll
    for (int e = 0; e < 8; e++) {
        int rr = (e < 4) ? rr0 : rr0 + 64;
        int col = q * 4 + (e & 3);
        int ks = col >> 3, cc = col & 7;
        int mt = rr >> 4, r = rr & 15;
        int lw = ((r & 7) << 2) | (cc & 3);
        int slot = ((cc >> 2) << 1) | (r >> 3);
        aoff[e] = ((mt * 2 + ks) << 7) + (lw << 2) + slot;
    }

    float acc[4][4][4];
#pragma unroll
    for (int i = 0; i < 4; i++)
#pragma unroll
        for (int j = 0; j < 4; j++)
#pragma unroll
            for (int v = 0; v < 4; v++) acc[i][j][v] = 0.f;

    float4 sa0, sa1, sb[2];

    sa0 = *(const float4*)(A + (size_t)(row0 + rr0) * DD + q * 4);
    sa1 = *(const float4*)(A + (size_t)(row0 + rr0 + 64) * DD + q * 4);
#pragma unroll
    for (int i = 0; i < 2; i++)
        sb[i] = __ldg((const float4*)(r12_bfrag + (size_t)(tid + i * 256) * 4));

    {
        float* st = r12_dsm;
        float av[8] = {sa0.x, sa0.y, sa0.z, sa0.w, sa1.x, sa1.y, sa1.z, sa1.w};
#pragma unroll
        for (int e = 0; e < 8; e++) st[aoff[e]] = r12_tf32(av[e]);
#pragma unroll
        for (int i = 0; i < 2; i++)
            *(float4*)(st + AFRAG + (tid + i * 256) * 4) = sb[i];
    }
    __syncthreads();

    for (int c = 0; c < NCH; ++c) {
        const int cur = c & 1;
        const float* st = r12_dsm + cur * STAGEF;

        if (c + 1 < NCH) {
            int k0 = (c + 1) * KC;
            sa0 = *(const float4*)(A + (size_t)(row0 + rr0) * DD + k0 + q * 4);
            sa1 = *(const float4*)(A + (size_t)(row0 + rr0 + 64) * DD + k0 + q * 4);
#pragma unroll
            for (int i = 0; i < 2; i++)
                sb[i] = __ldg((const float4*)(r12_bfrag + (size_t)(c + 1) * BFRAG + (size_t)(tid + i * 256) * 4));
        }

#pragma unroll
        for (int ks = 0; ks < 2; ks++) {
            const float* Ab = st;
            const float* Bb = st + AFRAG;
            uint32_t a0[4][4], b0[4][2];
#pragma unroll
            for (int mt = 0; mt < 4; mt++) {
                float4 v = *(const float4*)(Ab + (((wy * 4 + mt) * 2 + ks) << 7) + (lane << 2));
                a0[mt][0] = __float_as_uint(v.x); a0[mt][1] = __float_as_uint(v.y);
                a0[mt][2] = __float_as_uint(v.z); a0[mt][3] = __float_as_uint(v.w);
            }
#pragma unroll
            for (int nt = 0; nt < 4; nt++) {
                float2 v = *(const float2*)(Bb + (((wx * 4 + nt) * 2 + ks) << 6) + (lane << 1));
                b0[nt][0] = __float_as_uint(v.x); b0[nt][1] = __float_as_uint(v.y);
            }
#pragma unroll
            for (int mt = 0; mt < 4; mt++)
#pragma unroll
                for (int nt = 0; nt < 4; nt++)
                    r12_mma(acc[mt][nt], a0[mt], b0[nt]);
        }

        if (c + 1 < NCH) {
            float* st2 = r12_dsm + (cur ^ 1) * STAGEF;
            float av[8] = {sa0.x, sa0.y, sa0.z, sa0.w, sa1.x, sa1.y, sa1.z, sa1.w};
#pragma unroll
            for (int e = 0; e < 8; e++) st2[aoff[e]] = r12_tf32(av[e]);
#pragma unroll
            for (int i = 0; i < 2; i++)
                *(float4*)(st2 + AFRAG + (tid + i * 256) * 4) = sb[i];
        }
        __syncthreads();
    }

    const int mrow = lane >> 2;
    const int kcol = lane & 3;
#pragma unroll
    for (int mt = 0; mt < 4; mt++)
#pragma unroll
        for (int h = 0; h < 2; h++) {
            int row = (wy * 4 + mt) * 16 + mrow + 8 * h;
            float part = 0.f;
#pragma unroll
            for (int nt = 0; nt < 4; nt++) {
                int col = (wx * 4 + nt) * 8 + 2 * kcol;
                float x0 = acc[mt][nt][2 * h]     + b1s[col];
                float x1 = acc[mt][nt][2 * h + 1] + b1s[col + 1];
                float g0 = 0.5f * x0 * (1.0f + erff(x0 * 0.7071067811865476f));
                float g1 = 0.5f * x1 * (1.0f + erff(x1 * 0.7071067811865476f));
                part = fmaf(g0, w2s[col], part);
                part = fmaf(g1, w2s[col + 1], part);
            }
            red[row * 17 + wx * 4 + kcol] = part;
        }
    __syncthreads();

    if (tid < 128) {
        float s = bias2[0];
#pragma unroll
        for (int j = 0; j < 16; j++) s += red[tid * 17 + j];
        scores_out[row0 + tid] = s;
        r12_scores[row0 + tid] = s;
    }
}

// ---------------------------------------------------------------------------
// Kernel 2: per-batch bitonic sort of approx scores -> top-NCAND candidates.
// ---------------------------------------------------------------------------
__global__ __launch_bounds__(1024) void r12_cand_topk(const int* __restrict__ mask)
{
    __shared__ ull key[SS];
    __shared__ int sh_cnt;
    const int b = blockIdx.x;
    const int tid = threadIdx.x;
    if (tid == 0) sh_cnt = 0;
    __syncthreads();

    const float* srow = r12_scores + (size_t)b * SS;
    const int*   mrow = mask + (size_t)b * SS;

    int cnt = 0;
    for (int i = tid; i < SS; i += 1024) {
        float f = srow[i];
        unsigned u = __float_as_uint(f);
        u = (u & 0x80000000u) ? ~u : (u | 0x80000000u);
        key[i] = ((ull)u << 12) | (ull)(SS - 1 - i);
        cnt += mrow[i];
    }
#pragma unroll
    for (int o = 16; o > 0; o >>= 1) cnt += __shfl_down_sync(0xffffffffu, cnt, o);
    if ((tid & 31) == 0) atomicAdd(&sh_cnt, cnt);
    __syncthreads();

    for (int k = 2; k <= SS; k <<= 1) {
        for (int j = k >> 1; j > 0; j >>= 1) {
            for (int i = tid; i < SS; i += 1024) {
                int l = i ^ j;
                if (l > i) {
                    ull a = key[i], cc = key[l];
                    bool desc = ((i & k) == 0);
                    if (desc ? (a < cc) : (a > cc)) { key[i] = cc; key[l] = a; }
                }
            }
            __syncthreads();
        }
    }

    if (tid == 0) {
        int ntok = sh_cnt;
        int nn = (int)ceilf((float)ntok * 0.1f);
        nn = max(nn, 1);
        nn = min(nn, ntok);
        r12_nn[b] = nn;
    }
    if (tid < NCAND)
        r12_cand[b * NCAND + tid] = (SS - 1) - (int)(key[tid] & 0xFFFull);
}

// ---------------------------------------------------------------------------
// Kernel 3: exact fp32 rescore (serial ascending-k fmaf chain per candidate).
// 128 threads = hidden cols; CPB=16 candidates; smem A transposed [k][cand]
// with 18-float stride -> 8B-aligned pair loads (LDS.64), coalesced w1 LDG.
// ---------------------------------------------------------------------------
__global__ __launch_bounds__(128) void r12_rescore(
    const float* __restrict__ lhs, const float* __restrict__ w1,
    const float* __restrict__ bias1, const float* __restrict__ w2v,
    const float* __restrict__ bias2)
{
    __shared__ float sA[128][ASTRIDE];   // [k within chunk][cand]
    __shared__ float sp[128][CPB];
    __shared__ int rows[CPB];

    const int blk = blockIdx.x;          // 0 .. BB*NCAND/CPB-1
    const int tid = threadIdx.x;         // hidden col j
    const int cand0 = blk * CPB;
    const int b = cand0 / NCAND;

    if (tid < CPB) rows[tid] = r12_cand[cand0 + tid];

    ull h2[CPB / 2];
#pragma unroll
    for (int r = 0; r < CPB / 2; r++) h2[r] = 0ull;

    for (int ch = 0; ch < DD / 128; ch++) {
        __syncthreads();
        // load 16 candidate rows x 128 cols, transposed into sA[k][r]
#pragma unroll
        for (int p = 0; p < 4; p++) {
            int lin = tid + p * 128;     // 0..511
            int r = lin >> 5, qq = lin & 31;
            float4 v = *(const float4*)(lhs + ((size_t)b * SS + rows[r]) * DD + ch * 128 + qq * 4);
            sA[qq * 4 + 0][r] = v.x;
            sA[qq * 4 + 1][r] = v.y;
            sA[qq * 4 + 2][r] = v.z;
            sA[qq * 4 + 3][r] = v.w;
        }
        __syncthreads();

#pragma unroll 4
        for (int k = 0; k < 128; k++) {
            float w = __ldg(w1 + (size_t)(ch * 128 + k) * HH + tid);  // coalesced
            ull wp = r12_pack2(w, w);
            const ull* ap = (const ull*)(&sA[k][0]);    // 8B-aligned (stride 18)
#pragma unroll
            for (int j = 0; j < CPB / 2; j++)
                r12_ffma2(h2[j], ap[j], wp);
        }
    }

    float b1v = bias1[tid], w2vv = w2v[tid];
#pragma unroll
    for (int r2 = 0; r2 < CPB / 2; r2++) {
        float x0, x1;
        r12_unpack2(h2[r2], x0, x1);
        x0 += b1v; x1 += b1v;
        float g0 = 0.5f * x0 * (1.0f + erff(x0 * 0.7071067811865476f));
        float g1 = 0.5f * x1 * (1.0f + erff(x1 * 0.7071067811865476f));
        sp[tid][2 * r2]     = g0 * w2vv;
        sp[tid][2 * r2 + 1] = g1 * w2vv;
    }
    __syncthreads();

    if (tid < CPB) {
        float s = bias2[0];
        for (int j = 0; j < 128; j++) s += sp[j][tid];
        r12_cscore[cand0 + tid] = s;
    }
}

// ---------------------------------------------------------------------------
// Kernel 4: final per-batch sort of NCAND rescored candidates -> outputs.
// ---------------------------------------------------------------------------
__global__ __launch_bounds__(NCAND) void r12_final(
    float* __restrict__ o_mask, float* __restrict__ o_ns, float* __restrict__ o_idx)
{
    __shared__ ull key[NCAND];
    const int b = blockIdx.x;
    const int tid = threadIdx.x;

    {
        float f = r12_cscore[b * NCAND + tid];
        int idx = r12_cand[b * NCAND + tid];
        unsigned u = __float_as_uint(f);
        u = (u & 0x80000000u) ? ~u : (u | 0x80000000u);
        key[tid] = ((ull)u << 12) | (ull)(SS - 1 - idx);
    }
    __syncthreads();

    for (int k = 2; k <= NCAND; k <<= 1) {
        for (int j = k >> 1; j > 0; j >>= 1) {
            int l = tid ^ j;
            if (l > tid) {
                ull a = key[tid], cc = key[l];
                bool desc = ((tid & k) == 0);
                if (desc ? (a < cc) : (a > cc)) { key[tid] = cc; key[l] = a; }
            }
            __syncthreads();
        }
    }

    if (tid < MN) {
        ull kk = key[tid];
        int idx = (SS - 1) - (int)(kk & 0xFFFull);
        unsigned u = (unsigned)(kk >> 12);
        u = (u & 0x80000000u) ? (u & 0x7FFFFFFFu) : ~u;
        int nn = r12_nn[b];
        o_idx[b * MN + tid]  = (float)idx;
        o_ns[b * MN + tid]   = __uint_as_float(u);
        o_mask[b * MN + tid] = (tid < nn) ? 1.0f : 0.0f;
        r12_idx[b * MN + tid] = idx;
    }
}

// ---------------------------------------------------------------------------
// Kernel 5: gather enc rows.
// ---------------------------------------------------------------------------
__global__ __launch_bounds__(512) void r12_gather(
    const float* __restrict__ hidden, float* __restrict__ enc)
{
    int t = blockIdx.x;
    int b = t / MN;
    int s = r12_idx[t];
    const float4* src = (const float4*)(hidden + ((size_t)b * SS + s) * DD);
    float4* dst = (float4*)(enc + (size_t)t * DD);
    dst[threadIdx.x] = src[threadIdx.x];
}

// ---------------------------------------------------------------------------
extern "C" void kernel_launch(void* const* d_in, const int* in_sizes, int n_in,
                              void* d_out, int out_size)
{
    const float* lhs  = (const float*)d_in[0];
    const float* hid  = (const float*)d_in[1];
    const int*   mask = (const int*)  d_in[2];
    const float* w1   = (const float*)d_in[3];
    const float* b1   = (const float*)d_in[4];
    const float* w2   = (const float*)d_in[5];
    const float* b2   = (const float*)d_in[6];

    float* out = (float*)d_out;
    float* o_enc    = out;
    float* o_mask   = out + ENC_SZ;
    float* o_ns     = o_mask + BMN;
    float* o_idx    = o_ns + BMN;
    float* o_scores = o_idx + BMN;

    cudaFuncSetAttribute(r12_score,
                         cudaFuncAttributeMaxDynamicSharedMemorySize, SMEM_BYTES);

    r12_bprep<<<(HH * DD) / 256, 256>>>(w1);
    r12_score<<<MM / 128, 256, SMEM_BYTES>>>(lhs, b1, w2, b2, o_scores);
    r12_cand_topk<<<BB, 1024>>>(mask);
    r12_rescore<<<BB * NCAND / CPB, 128>>>(lhs, w1, b1, w2, b2);
    r12_final<<<BB, NCAND>>>(o_mask, o_ns, o_idx);
    r12_gather<<<BB * MN, 512>>>(hid, o_enc);
}